// round 8
// baseline (speedup 1.0000x reference)
#include <cuda_runtime.h>
#include <cstdint>

// ---------------------------------------------------------------------------
// Threefry-2x32, FULL 20 rounds + 6 key injections (bit-exact JAX).
// ---------------------------------------------------------------------------
#define TF_ROUND(r) do { x0 += x1; x1 = (x1 << (r)) | (x1 >> (32 - (r))); x1 ^= x0; } while (0)

__host__ __device__ __forceinline__ void tf2x32(uint32_t k0, uint32_t k1,
                                                uint32_t x0, uint32_t x1,
                                                uint32_t& o0, uint32_t& o1) {
    uint32_t k2 = k0 ^ k1 ^ 0x1BD11BDAu;
    x0 += k0; x1 += k1;
    TF_ROUND(13); TF_ROUND(15); TF_ROUND(26); TF_ROUND(6);
    x0 += k1; x1 += k2 + 1u;
    TF_ROUND(17); TF_ROUND(29); TF_ROUND(16); TF_ROUND(24);
    x0 += k2; x1 += k0 + 2u;
    TF_ROUND(13); TF_ROUND(15); TF_ROUND(26); TF_ROUND(6);
    x0 += k0; x1 += k1 + 3u;
    TF_ROUND(17); TF_ROUND(29); TF_ROUND(16); TF_ROUND(24);
    x0 += k1; x1 += k2 + 4u;
    TF_ROUND(13); TF_ROUND(15); TF_ROUND(26); TF_ROUND(6);
    x0 += k2; x1 += k0 + 5u;
    o0 = x0; o1 = x1;
}

__device__ __forceinline__ uint32_t tfbits(uint32_t k0, uint32_t k1, uint32_t j) {
    uint32_t o0, o1;
    tf2x32(k0, k1, 0u, j, o0, o1);
    return o0 ^ o1;
}

__device__ __forceinline__ float jax_uniform(uint32_t bits) {
    const float TINY = 1.17549435e-38f;
    float f = __uint_as_float((bits >> 9) | 0x3f800000u) - 1.0f;
    return fmaxf(TINY, f + TINY);
}

// argmax(c + gumbel) over 2; index-0 wins ties. Equal counts -> exact bit compare.
__device__ __forceinline__ bool decide(float c0, float c1, uint32_t b0, uint32_t b1) {
    if (c0 == c1) return (b1 >> 9) > (b0 >> 9);
    float g0 = -logf(-logf(jax_uniform(b0)));
    float g1 = -logf(-logf(jax_uniform(b1)));
    return (c1 + g1) > (c0 + g0);
}

// ---------------------------------------------------------------------------
#define B_SZ  128
#define F0    1024
#define F1    512

__device__ int                 g_op0[F1];
__device__ int                 g_op1[F0];
__device__ uint32_t            g_mask0[F1 * (F0 / 32)];   // 64 KB, 128B per row
__device__ uint32_t            g_mask1[F0 * (F1 / 32)];   // 64 KB, 64B per row
__device__ unsigned long long  g_skey0[B_SZ * F0];        // sorted keys, [b][k]

// ---------------------------------------------------------------------------
// MEGA kernel (512 threads, 640 blocks):
//   blocks [0,128)   : sort layer-0 input rows
//   blocks [128,384) : layer-0 masks, 4 edges/thread (2 neurons/block)
//   blocks [384,640) : layer-1 masks, 4 edges/thread (4 neurons/block)
// ---------------------------------------------------------------------------
__global__ __launch_bounds__(512) void mega_kernel(
        const float* __restrict__ x,
        const float* __restrict__ etc0, const float* __restrict__ otc0,
        const float* __restrict__ etc1, const float* __restrict__ otc1,
        uint32_t op0k0, uint32_t op0k1, uint32_t e0k0, uint32_t e0k1,
        uint32_t op1k0, uint32_t op1k1, uint32_t e1k0, uint32_t e1k1) {
    __shared__ unsigned long long a[1024];
    int bid = blockIdx.x;
    int tid = threadIdx.x;

    if (bid < B_SZ) {
        int b = bid;
        #pragma unroll
        for (int r = 0; r < 2; ++r) {
            int idx = tid + r * 512;
            float v = fmaxf(x[(size_t)b * F0 + idx], 0.0f);
            a[idx] = ((unsigned long long)__float_as_uint(v) << 32) | (unsigned)idx;
        }
        __syncthreads();
        for (int k = 2; k <= F0; k <<= 1) {
            for (int j = k >> 1; j > 0; j >>= 1) {
                #pragma unroll
                for (int r = 0; r < 2; ++r) {
                    int s = tid + r * 512;
                    int l = s ^ j;
                    if (l > s) {
                        bool up = ((s & k) == 0);
                        unsigned long long va = a[s], vb = a[l];
                        if ((va > vb) == up) { a[s] = vb; a[l] = va; }
                    }
                }
                __syncthreads();
            }
        }
        #pragma unroll
        for (int r = 0; r < 2; ++r) {
            int idx = tid + r * 512;
            g_skey0[(size_t)b * F0 + idx] = a[idx];
        }
        return;
    }

    // ---- mask blocks: 4 edges per thread ----
    int warp = tid >> 5, lane = tid & 31;
    int o, wslice, log2in;
    const float* etc; const float* otc;
    uint32_t ek0, ek1, opk0, opk1;
    uint32_t* maskb; int* oparr;
    if (bid < 384) {              // layer 0: out=512, in=1024, 8 warps per o
        int q = bid - 128;
        o = q * 2 + (warp >> 3); wslice = warp & 7;
        log2in = 10; etc = etc0; otc = otc0;
        ek0 = e0k0; ek1 = e0k1; opk0 = op0k0; opk1 = op0k1;
        maskb = g_mask0; oparr = g_op0;
    } else {                      // layer 1: out=1024, in=512, 4 warps per o
        int q = bid - 384;
        o = q * 4 + (warp >> 2); wslice = warp & 3;
        log2in = 9; etc = etc1; otc = otc1;
        ek0 = e1k0; ek1 = e1k1; opk0 = op1k0; opk1 = op1k1;
        maskb = g_mask1; oparr = g_op1;
    }

    // operator selection: lanes 0/1 compute one draw each, shfl both
    uint32_t jv = tfbits(opk0, opk1, (uint32_t)(2 * o) + (uint32_t)(lane & 1));
    uint32_t ob0 = __shfl_sync(0xffffffffu, jv, 0);
    uint32_t ob1 = __shfl_sync(0xffffffffu, jv, 1);
    int op = decide(otc[2 * o], otc[2 * o + 1], ob0, ob1) ? 1 : 0;
    if (wslice == 0 && lane == 0) oparr[o] = op;

    int nw = 1 << (log2in - 5);
    uint32_t mbase = ((uint32_t)(o * 2 + op)) << log2in;
    const float2* etc2 = (const float2*)etc;

    #pragma unroll
    for (int c = 0; c < 4; ++c) {
        int i = wslice * 128 + c * 32 + lane;
        uint32_t m = mbase + (uint32_t)i;
        uint32_t b0 = tfbits(ek0, ek1, 2u * m);        // et=0 (no_edge)
        uint32_t b1 = tfbits(ek0, ek1, 2u * m + 1u);   // et=1 (normal_edge)
        float2 cc = etc2[m];
        bool sel = decide(cc.x, cc.y, b0, b1);
        unsigned msk = __ballot_sync(0xffffffffu, sel);
        if (lane == 0) maskb[o * nw + (i >> 5)] = msk;
    }
}

// ---------------------------------------------------------------------------
// Warp-cooperative probe: 32 lanes test 32 consecutive sorted keys; mask words
// all land in ONE mask row (<=128B => 1 line per LDG). Ballot picks winner.
// ---------------------------------------------------------------------------
__device__ __forceinline__ float probe_warp(const unsigned long long* __restrict__ a,
                                            int n, const uint32_t* __restrict__ mrow,
                                            int op, int lane) {
    if (op == 0) {                       // min: first selected, ascending
        for (int base = 0; base < n; base += 32) {
            unsigned long long kv = a[base + lane];
            unsigned idx = (unsigned)kv;
            uint32_t bit = (__ldg(mrow + (idx >> 5)) >> (idx & 31)) & 1u;
            unsigned bal = __ballot_sync(0xffffffffu, bit);
            if (bal) {
                int src = __ffs(bal) - 1;
                unsigned vb = __shfl_sync(0xffffffffu, (unsigned)(kv >> 32), src);
                return __uint_as_float(vb);
            }
        }
        return 1.0f;
    } else {                             // max: last selected, descending
        for (int base = n - 32; base >= 0; base -= 32) {
            unsigned long long kv = a[base + lane];
            unsigned idx = (unsigned)kv;
            uint32_t bit = (__ldg(mrow + (idx >> 5)) >> (idx & 31)) & 1u;
            unsigned bal = __ballot_sync(0xffffffffu, bit);
            if (bal) {
                int src = 31 - __clz(bal);
                unsigned vb = __shfl_sync(0xffffffffu, (unsigned)(kv >> 32), src);
                return __uint_as_float(vb);
            }
        }
        return 0.0f;
    }
}

// shfl compare-exchange step for one (k, j<32) bitonic phase.
__device__ __forceinline__ unsigned long long bitonic_shfl_step(
        unsigned long long v, int t, int k, int j) {
    unsigned long long pv = __shfl_xor_sync(0xffffffffu, v, j);
    bool up = ((t & k) == 0);
    bool keepMin = (((t & j) == 0) == up);
    unsigned long long lo = v < pv ? v : pv;
    unsigned long long hi = v < pv ? pv : v;
    return keepMin ? lo : hi;
}

// ---------------------------------------------------------------------------
// FUSED kernel (512 threads, 256 blocks = 2 per batch row):
//  1) load sorted layer-0 keys into smem
//  2) probe layer-0: warp w handles neurons [w*32, w*32+32); lane t keeps
//     the result of neuron w*32+t  -> register v = hidden key for index tid
//  3) bitonic sort 512 keys (registers + smem hybrid)
//  4) probe layer-1 (this block's half, warp-cooperative) -> out
// ---------------------------------------------------------------------------
__global__ __launch_bounds__(512) void fused_kernel(float* __restrict__ out) {
    __shared__ unsigned long long a[1024];
    __shared__ unsigned long long hk[512];
    int row  = blockIdx.x >> 1;
    int half = blockIdx.x & 1;
    int tid  = threadIdx.x;
    int warp = tid >> 5, lane = tid & 31;

    // 1) coalesced 16B loads of sorted row (1024 keys = 512 uint4)
    {
        const uint4* src = (const uint4*)(g_skey0 + (size_t)row * F0);
        ((uint4*)a)[tid] = src[tid];
    }
    __syncthreads();

    // 2) probe layer 0, warp-cooperative; lane t keeps neuron (warp*32+t)
    unsigned long long v = 0;
    {
        int obase = warp * 32;
        #pragma unroll 4
        for (int t = 0; t < 32; ++t) {
            int o = obase + t;
            int op = g_op0[o];
            float res = probe_warp(a, F0, g_mask0 + o * (F0 / 32), op, lane);
            if (lane == t)
                v = ((unsigned long long)__float_as_uint(res) << 32) | (unsigned)o;
        }
    }

    // 3a) bitonic k = 2..32 in registers via shfl (no barriers)
    #pragma unroll
    for (int k = 2; k <= 32; k <<= 1)
        #pragma unroll
        for (int j = k >> 1; j > 0; j >>= 1)
            v = bitonic_shfl_step(v, tid, k, j);

    hk[tid] = v;
    __syncthreads();

    // 3b) k = 64..512: cross-warp phases in smem, then j<32 in registers
    #pragma unroll
    for (int k = 64; k <= 512; k <<= 1) {
        for (int j = k >> 1; j >= 32; j >>= 1) {
            int s = tid, l = tid ^ j;
            if (l > s) {
                bool up = ((s & k) == 0);
                unsigned long long va = hk[s], vb = hk[l];
                if ((va > vb) == up) { hk[s] = vb; hk[l] = va; }
            }
            __syncthreads();
        }
        v = hk[tid];
        #pragma unroll
        for (int j = 16; j > 0; j >>= 1)
            v = bitonic_shfl_step(v, tid, k, j);
        hk[tid] = v;
        __syncthreads();
    }

    // 4) probe layer 1, warp-cooperative, this block's half of the neurons;
    //    lane t keeps neuron (half*512 + warp*32 + t), then coalesced store.
    {
        int obase = half * 512 + warp * 32;
        float myres = 0.0f;
        #pragma unroll 4
        for (int t = 0; t < 32; ++t) {
            int o = obase + t;
            int op = g_op1[o];
            float res = probe_warp(hk, F1, g_mask1 + o * (F1 / 32), op, lane);
            if (lane == t) myres = res;
        }
        out[(size_t)row * F0 + obase + lane] = myres;
    }
}

// ---------------------------------------------------------------------------
extern "C" void kernel_launch(void* const* d_in, const int* in_sizes, int n_in,
                              void* d_out, int out_size) {
    const float* x    = (const float*)d_in[0];
    const float* etc0 = (const float*)d_in[1];
    const float* otc0 = (const float*)d_in[2];
    const float* etc1 = (const float*)d_in[3];
    const float* otc1 = (const float*)d_in[4];
    float* out = (float*)d_out;

    // JAX key chain (partitionable), base = key(42) = (0, 42)
    uint32_t l0k0, l0k1, l1k0, l1k1;
    tf2x32(0u, 42u, 0u, 0u, l0k0, l0k1);
    tf2x32(0u, 42u, 0u, 1u, l1k0, l1k1);
    uint32_t op0k0, op0k1, e0k0, e0k1;
    tf2x32(l0k0, l0k1, 0u, 0u, op0k0, op0k1);
    tf2x32(l0k0, l0k1, 0u, 1u, e0k0,  e0k1);
    uint32_t op1k0, op1k1, e1k0, e1k1;
    tf2x32(l1k0, l1k1, 0u, 0u, op1k0, op1k1);
    tf2x32(l1k0, l1k1, 0u, 1u, e1k0,  e1k1);

    // 1) input-only work: sort0 + ops + masks (both layers)
    mega_kernel<<<640, 512>>>(x, etc0, otc0, etc1, otc1,
                              op0k0, op0k1, e0k0, e0k1,
                              op1k0, op1k1, e1k0, e1k1);
    // 2) everything else, fused per batch row (2 blocks per row)
    fused_kernel<<<256, 512>>>(out);
}

// round 9
// speedup vs baseline: 1.6975x; 1.6975x over previous
#include <cuda_runtime.h>
#include <cstdint>

// ---------------------------------------------------------------------------
// Threefry-2x32, FULL 20 rounds + 6 key injections (bit-exact JAX).
// ---------------------------------------------------------------------------
#define TF_ROUND(r) do { x0 += x1; x1 = (x1 << (r)) | (x1 >> (32 - (r))); x1 ^= x0; } while (0)

__host__ __device__ __forceinline__ void tf2x32(uint32_t k0, uint32_t k1,
                                                uint32_t x0, uint32_t x1,
                                                uint32_t& o0, uint32_t& o1) {
    uint32_t k2 = k0 ^ k1 ^ 0x1BD11BDAu;
    x0 += k0; x1 += k1;
    TF_ROUND(13); TF_ROUND(15); TF_ROUND(26); TF_ROUND(6);
    x0 += k1; x1 += k2 + 1u;
    TF_ROUND(17); TF_ROUND(29); TF_ROUND(16); TF_ROUND(24);
    x0 += k2; x1 += k0 + 2u;
    TF_ROUND(13); TF_ROUND(15); TF_ROUND(26); TF_ROUND(6);
    x0 += k0; x1 += k1 + 3u;
    TF_ROUND(17); TF_ROUND(29); TF_ROUND(16); TF_ROUND(24);
    x0 += k1; x1 += k2 + 4u;
    TF_ROUND(13); TF_ROUND(15); TF_ROUND(26); TF_ROUND(6);
    x0 += k2; x1 += k0 + 5u;
    o0 = x0; o1 = x1;
}

__device__ __forceinline__ uint32_t tfbits(uint32_t k0, uint32_t k1, uint32_t j) {
    uint32_t o0, o1;
    tf2x32(k0, k1, 0u, j, o0, o1);
    return o0 ^ o1;
}

__device__ __forceinline__ float jax_uniform(uint32_t bits) {
    const float TINY = 1.17549435e-38f;
    float f = __uint_as_float((bits >> 9) | 0x3f800000u) - 1.0f;
    return fmaxf(TINY, f + TINY);
}

__device__ __forceinline__ bool decide(float c0, float c1, uint32_t b0, uint32_t b1) {
    if (c0 == c1) return (b1 >> 9) > (b0 >> 9);
    float g0 = -logf(-logf(jax_uniform(b0)));
    float g1 = -logf(-logf(jax_uniform(b1)));
    return (c1 + g1) > (c0 + g0);
}

// ---------------------------------------------------------------------------
#define B_SZ  128
#define F0    1024
#define F1    512

__device__ int                 g_op0[F1];
__device__ int                 g_op1[F0];
__device__ uint32_t            g_mask0[F1 * (F0 / 32)];   // 64 KB
__device__ uint32_t            g_mask1[F0 * (F1 / 32)];   // 64 KB
__device__ unsigned long long  g_skey0[B_SZ * F0];        // sorted keys, [b][k]

// ---------------------------------------------------------------------------
// MEGA kernel (512 threads, 640 blocks): unchanged from R6 (proven).
// ---------------------------------------------------------------------------
__global__ __launch_bounds__(512) void mega_kernel(
        const float* __restrict__ x,
        const float* __restrict__ etc0, const float* __restrict__ otc0,
        const float* __restrict__ etc1, const float* __restrict__ otc1,
        uint32_t op0k0, uint32_t op0k1, uint32_t e0k0, uint32_t e0k1,
        uint32_t op1k0, uint32_t op1k1, uint32_t e1k0, uint32_t e1k1) {
    __shared__ unsigned long long a[1024];
    int bid = blockIdx.x;
    int tid = threadIdx.x;

    if (bid < B_SZ) {
        int b = bid;
        #pragma unroll
        for (int r = 0; r < 2; ++r) {
            int idx = tid + r * 512;
            float v = fmaxf(x[(size_t)b * F0 + idx], 0.0f);
            a[idx] = ((unsigned long long)__float_as_uint(v) << 32) | (unsigned)idx;
        }
        __syncthreads();
        for (int k = 2; k <= F0; k <<= 1) {
            for (int j = k >> 1; j > 0; j >>= 1) {
                #pragma unroll
                for (int r = 0; r < 2; ++r) {
                    int s = tid + r * 512;
                    int l = s ^ j;
                    if (l > s) {
                        bool up = ((s & k) == 0);
                        unsigned long long va = a[s], vb = a[l];
                        if ((va > vb) == up) { a[s] = vb; a[l] = va; }
                    }
                }
                __syncthreads();
            }
        }
        #pragma unroll
        for (int r = 0; r < 2; ++r) {
            int idx = tid + r * 512;
            g_skey0[(size_t)b * F0 + idx] = a[idx];
        }
        return;
    }

    int warp = tid >> 5, lane = tid & 31;
    int o, wslice, log2in;
    const float* etc; const float* otc;
    uint32_t ek0, ek1, opk0, opk1;
    uint32_t* maskb; int* oparr;
    if (bid < 384) {              // layer 0: out=512, in=1024, 8 warps per o
        int q = bid - 128;
        o = q * 2 + (warp >> 3); wslice = warp & 7;
        log2in = 10; etc = etc0; otc = otc0;
        ek0 = e0k0; ek1 = e0k1; opk0 = op0k0; opk1 = op0k1;
        maskb = g_mask0; oparr = g_op0;
    } else {                      // layer 1: out=1024, in=512, 4 warps per o
        int q = bid - 384;
        o = q * 4 + (warp >> 2); wslice = warp & 3;
        log2in = 9; etc = etc1; otc = otc1;
        ek0 = e1k0; ek1 = e1k1; opk0 = op1k0; opk1 = op1k1;
        maskb = g_mask1; oparr = g_op1;
    }

    uint32_t jv = tfbits(opk0, opk1, (uint32_t)(2 * o) + (uint32_t)(lane & 1));
    uint32_t ob0 = __shfl_sync(0xffffffffu, jv, 0);
    uint32_t ob1 = __shfl_sync(0xffffffffu, jv, 1);
    int op = decide(otc[2 * o], otc[2 * o + 1], ob0, ob1) ? 1 : 0;
    if (wslice == 0 && lane == 0) oparr[o] = op;

    int nw = 1 << (log2in - 5);
    uint32_t mbase = ((uint32_t)(o * 2 + op)) << log2in;
    const float2* etc2 = (const float2*)etc;

    #pragma unroll
    for (int c = 0; c < 4; ++c) {
        int i = wslice * 128 + c * 32 + lane;
        uint32_t m = mbase + (uint32_t)i;
        uint32_t b0 = tfbits(ek0, ek1, 2u * m);
        uint32_t b1 = tfbits(ek0, ek1, 2u * m + 1u);
        float2 cc = etc2[m];
        bool sel = decide(cc.x, cc.y, b0, b1);
        unsigned msk = __ballot_sync(0xffffffffu, sel);
        if (lane == 0) maskb[o * nw + (i >> 5)] = msk;
    }
}

// ---------------------------------------------------------------------------
// cp.async helpers
// ---------------------------------------------------------------------------
__device__ __forceinline__ uint32_t smem_u32(const void* p) {
    return (uint32_t)__cvta_generic_to_shared(p);
}
__device__ __forceinline__ void cpa16(uint32_t s, const void* g) {
    asm volatile("cp.async.cg.shared.global [%0], [%1], 16;" :: "r"(s), "l"(g));
}
#define CPA_COMMIT() asm volatile("cp.async.commit_group;")
#define CPA_WAIT(n)  asm volatile("cp.async.wait_group %0;" :: "n"(n))

// ---------------------------------------------------------------------------
// Batched per-thread probe over smem keys + smem mask row (proven R6 form).
// ---------------------------------------------------------------------------
__device__ __forceinline__ float probe8(const unsigned long long* __restrict__ a,
                                        int n, const uint32_t* __restrict__ mrow,
                                        int op) {
    float res;
    if (op == 0) {
        res = 1.0f;
        for (int base = 0; base < n; base += 8) {
            unsigned long long kv[8];
            uint32_t w[8];
            #pragma unroll
            for (int t = 0; t < 8; ++t) kv[t] = a[base + t];
            #pragma unroll
            for (int t = 0; t < 8; ++t) {
                unsigned idx = (unsigned)kv[t];
                w[t] = mrow[idx >> 5] >> (idx & 31);
            }
            bool found = false;
            #pragma unroll
            for (int t = 0; t < 8; ++t)
                if (!found && (w[t] & 1u)) {
                    res = __uint_as_float((unsigned)(kv[t] >> 32));
                    found = true;
                }
            if (found) break;
        }
    } else {
        res = 0.0f;
        for (int base = n - 8; base >= 0; base -= 8) {
            unsigned long long kv[8];
            uint32_t w[8];
            #pragma unroll
            for (int t = 0; t < 8; ++t) kv[t] = a[base + 7 - t];
            #pragma unroll
            for (int t = 0; t < 8; ++t) {
                unsigned idx = (unsigned)kv[t];
                w[t] = mrow[idx >> 5] >> (idx & 31);
            }
            bool found = false;
            #pragma unroll
            for (int t = 0; t < 8; ++t)
                if (!found && (w[t] & 1u)) {
                    res = __uint_as_float((unsigned)(kv[t] >> 32));
                    found = true;
                }
            if (found) break;
        }
    }
    return res;
}

// shfl compare-exchange for one (k, j<32) bitonic phase (proven R7/R8).
__device__ __forceinline__ unsigned long long bitonic_shfl_step(
        unsigned long long v, int t, int k, int j) {
    unsigned long long pv = __shfl_xor_sync(0xffffffffu, v, j);
    bool up = ((t & k) == 0);
    bool keepMin = (((t & j) == 0) == up);
    unsigned long long lo = v < pv ? v : pv;
    unsigned long long hi = v < pv ? pv : v;
    return keepMin ? lo : hi;
}

// ---------------------------------------------------------------------------
// FUSED kernel: 128 blocks (1/row), 512 threads, 140KB dynamic smem.
// smem layout: a[1024] keys (8KB) | hk[512] (4KB) | m0 (64KB) | m1 (64KB)
// cp.async groups: (row keys), (mask0), (mask1) -> wait 1 before probe0,
// wait 0 before probe1 (mask1 streams in under probe0 + sort).
// ---------------------------------------------------------------------------
extern __shared__ __align__(16) char s_raw[];

__global__ __launch_bounds__(512) void fused_kernel(float* __restrict__ out) {
    unsigned long long* a  = (unsigned long long*)(s_raw);
    unsigned long long* hk = (unsigned long long*)(s_raw + 8192);
    uint32_t* m0s = (uint32_t*)(s_raw + 12288);
    uint32_t* m1s = (uint32_t*)(s_raw + 12288 + 65536);

    int row = blockIdx.x;
    int tid = threadIdx.x;

    // async loads: group1 = sorted row (8KB), group2 = mask0 (64KB), group3 = mask1 (64KB)
    {
        const char* gsk = (const char*)(g_skey0 + (size_t)row * F0);
        cpa16(smem_u32((char*)a + tid * 16), gsk + tid * 16);
        CPA_COMMIT();
        #pragma unroll
        for (int r = 0; r < 8; ++r)
            cpa16(smem_u32((char*)m0s + (tid + r * 512) * 16),
                  (const char*)g_mask0 + (tid + r * 512) * 16);
        CPA_COMMIT();
        #pragma unroll
        for (int r = 0; r < 8; ++r)
            cpa16(smem_u32((char*)m1s + (tid + r * 512) * 16),
                  (const char*)g_mask1 + (tid + r * 512) * 16);
        CPA_COMMIT();
    }
    CPA_WAIT(1);          // row + mask0 resident; mask1 still streaming
    __syncthreads();

    // probe layer 0 (1 neuron per thread), mask row in smem
    unsigned long long v;
    {
        int o = tid;
        int op = g_op0[o];
        float res = probe8(a, F0, m0s + o * (F0 / 32), op);
        v = ((unsigned long long)__float_as_uint(res) << 32) | (unsigned)o;
    }

    // bitonic sort of 512 hidden keys: k<=32 in registers (no barriers)
    #pragma unroll
    for (int k = 2; k <= 32; k <<= 1)
        #pragma unroll
        for (int j = k >> 1; j > 0; j >>= 1)
            v = bitonic_shfl_step(v, tid, k, j);

    hk[tid] = v;
    __syncthreads();

    // k = 64..512: cross-warp phases in smem, then j<32 in registers
    #pragma unroll
    for (int k = 64; k <= 512; k <<= 1) {
        for (int j = k >> 1; j >= 32; j >>= 1) {
            int s = tid, l = tid ^ j;
            if (l > s) {
                bool up = ((s & k) == 0);
                unsigned long long va = hk[s], vb = hk[l];
                if ((va > vb) == up) { hk[s] = vb; hk[l] = va; }
            }
            __syncthreads();
        }
        v = hk[tid];
        #pragma unroll
        for (int j = 16; j > 0; j >>= 1)
            v = bitonic_shfl_step(v, tid, k, j);
        hk[tid] = v;
        __syncthreads();
    }

    CPA_WAIT(0);          // mask1 resident
    __syncthreads();

    // probe layer 1 (2 neurons per thread) -> final output
    #pragma unroll
    for (int rep = 0; rep < 2; ++rep) {
        int o = tid + rep * 512;
        int op = g_op1[o];
        float res = probe8(hk, F1, m1s + o * (F1 / 32), op);
        out[(size_t)row * F0 + o] = res;
    }
}

// ---------------------------------------------------------------------------
extern "C" void kernel_launch(void* const* d_in, const int* in_sizes, int n_in,
                              void* d_out, int out_size) {
    const float* x    = (const float*)d_in[0];
    const float* etc0 = (const float*)d_in[1];
    const float* otc0 = (const float*)d_in[2];
    const float* etc1 = (const float*)d_in[3];
    const float* otc1 = (const float*)d_in[4];
    float* out = (float*)d_out;

    // JAX key chain (partitionable), base = key(42) = (0, 42)
    uint32_t l0k0, l0k1, l1k0, l1k1;
    tf2x32(0u, 42u, 0u, 0u, l0k0, l0k1);
    tf2x32(0u, 42u, 0u, 1u, l1k0, l1k1);
    uint32_t op0k0, op0k1, e0k0, e0k1;
    tf2x32(l0k0, l0k1, 0u, 0u, op0k0, op0k1);
    tf2x32(l0k0, l0k1, 0u, 1u, e0k0,  e0k1);
    uint32_t op1k0, op1k1, e1k0, e1k1;
    tf2x32(l1k0, l1k1, 0u, 0u, op1k0, op1k1);
    tf2x32(l1k0, l1k1, 0u, 1u, e1k0,  e1k1);

    static bool attr_set = false;
    if (!attr_set) {
        cudaFuncSetAttribute(fused_kernel,
                             cudaFuncAttributeMaxDynamicSharedMemorySize,
                             12288 + 65536 + 65536);
        attr_set = true;
    }

    mega_kernel<<<640, 512>>>(x, etc0, otc0, etc1, otc1,
                              op0k0, op0k1, e0k0, e0k1,
                              op1k0, op1k1, e1k0, e1k1);
    fused_kernel<<<B_SZ, 512, 12288 + 65536 + 65536>>>(out);
}

// round 10
// speedup vs baseline: 1.9923x; 1.1737x over previous
#include <cuda_runtime.h>
#include <cstdint>

// ---------------------------------------------------------------------------
// Threefry-2x32, FULL 20 rounds + 6 key injections (bit-exact JAX).
// ---------------------------------------------------------------------------
#define TF_ROUND(r) do { x0 += x1; x1 = (x1 << (r)) | (x1 >> (32 - (r))); x1 ^= x0; } while (0)

__host__ __device__ __forceinline__ void tf2x32(uint32_t k0, uint32_t k1,
                                                uint32_t x0, uint32_t x1,
                                                uint32_t& o0, uint32_t& o1) {
    uint32_t k2 = k0 ^ k1 ^ 0x1BD11BDAu;
    x0 += k0; x1 += k1;
    TF_ROUND(13); TF_ROUND(15); TF_ROUND(26); TF_ROUND(6);
    x0 += k1; x1 += k2 + 1u;
    TF_ROUND(17); TF_ROUND(29); TF_ROUND(16); TF_ROUND(24);
    x0 += k2; x1 += k0 + 2u;
    TF_ROUND(13); TF_ROUND(15); TF_ROUND(26); TF_ROUND(6);
    x0 += k0; x1 += k1 + 3u;
    TF_ROUND(17); TF_ROUND(29); TF_ROUND(16); TF_ROUND(24);
    x0 += k1; x1 += k2 + 4u;
    TF_ROUND(13); TF_ROUND(15); TF_ROUND(26); TF_ROUND(6);
    x0 += k2; x1 += k0 + 5u;
    o0 = x0; o1 = x1;
}

__device__ __forceinline__ uint32_t tfbits(uint32_t k0, uint32_t k1, uint32_t j) {
    uint32_t o0, o1;
    tf2x32(k0, k1, 0u, j, o0, o1);
    return o0 ^ o1;
}

__device__ __forceinline__ float jax_uniform(uint32_t bits) {
    const float TINY = 1.17549435e-38f;
    float f = __uint_as_float((bits >> 9) | 0x3f800000u) - 1.0f;
    return fmaxf(TINY, f + TINY);
}

__device__ __forceinline__ bool decide(float c0, float c1, uint32_t b0, uint32_t b1) {
    if (c0 == c1) return (b1 >> 9) > (b0 >> 9);
    float g0 = -logf(-logf(jax_uniform(b0)));
    float g1 = -logf(-logf(jax_uniform(b1)));
    return (c1 + g1) > (c0 + g0);
}

// ---------------------------------------------------------------------------
#define B_SZ  128
#define F0    1024
#define F1    512

__device__ int                 g_op0[F1];
__device__ int                 g_op1[F0];
// masks stored TRANSPOSED: g_mask0[w][o] (w<32, o<512), g_mask1[w][o] (w<16, o<1024)
__device__ uint32_t            g_mask0[(F0 / 32) * F1];   // 64 KB
__device__ uint32_t            g_mask1[(F1 / 32) * F0];   // 64 KB
__device__ unsigned long long  g_skey0[B_SZ * F0];

// shfl compare-exchange for one (k, j<=16) bitonic phase; s = element index.
__device__ __forceinline__ unsigned long long bitonic_shfl_step(
        unsigned long long v, int s, int k, int j) {
    unsigned long long pv = __shfl_xor_sync(0xffffffffu, v, j);
    bool up = ((s & k) == 0);
    bool keepMin = (((s & j) == 0) == up);
    unsigned long long lo = v < pv ? v : pv;
    unsigned long long hi = v < pv ? pv : v;
    return keepMin ? lo : hi;
}

// ---------------------------------------------------------------------------
// MEGA kernel (512 threads, 640 blocks):
//   blocks [0,128)   : sort layer-0 input rows (hybrid shfl bitonic, n=1024)
//   blocks [128,384) : layer-0 masks (transposed write)
//   blocks [384,640) : layer-1 masks (transposed write)
// ---------------------------------------------------------------------------
__global__ __launch_bounds__(512) void mega_kernel(
        const float* __restrict__ x,
        const float* __restrict__ etc0, const float* __restrict__ otc0,
        const float* __restrict__ etc1, const float* __restrict__ otc1,
        uint32_t op0k0, uint32_t op0k1, uint32_t e0k0, uint32_t e0k1,
        uint32_t op1k0, uint32_t op1k1, uint32_t e1k0, uint32_t e1k1) {
    __shared__ unsigned long long a[1024];
    int bid = blockIdx.x;
    int tid = threadIdx.x;

    if (bid < B_SZ) {
        int b = bid;
        // load 2 elements per thread
        float v0 = fmaxf(x[(size_t)b * F0 + tid], 0.0f);
        float v1 = fmaxf(x[(size_t)b * F0 + tid + 512], 0.0f);
        unsigned long long e0 = ((unsigned long long)__float_as_uint(v0) << 32) | (unsigned)tid;
        unsigned long long e1 = ((unsigned long long)__float_as_uint(v1) << 32) | (unsigned)(tid + 512);

        // k = 2..32 entirely in registers (both slots), no barriers
        #pragma unroll
        for (int k = 2; k <= 32; k <<= 1)
            #pragma unroll
            for (int j = k >> 1; j > 0; j >>= 1) {
                e0 = bitonic_shfl_step(e0, tid, k, j);
                e1 = bitonic_shfl_step(e1, tid + 512, k, j);
            }
        a[tid] = e0; a[tid + 512] = e1;
        __syncthreads();

        // k = 64..512: j>=32 in smem, j<=16 in registers
        #pragma unroll
        for (int k = 64; k <= 512; k <<= 1) {
            for (int j = k >> 1; j >= 32; j >>= 1) {
                #pragma unroll
                for (int r = 0; r < 2; ++r) {
                    int s = tid + r * 512;
                    int l = s ^ j;
                    if (l > s) {
                        bool up = ((s & k) == 0);
                        unsigned long long va = a[s], vb = a[l];
                        if ((va > vb) == up) { a[s] = vb; a[l] = va; }
                    }
                }
                __syncthreads();
            }
            e0 = a[tid]; e1 = a[tid + 512];
            #pragma unroll
            for (int j = 16; j > 0; j >>= 1) {
                e0 = bitonic_shfl_step(e0, tid, k, j);
                e1 = bitonic_shfl_step(e1, tid + 512, k, j);
            }
            a[tid] = e0; a[tid + 512] = e1;
            __syncthreads();
        }

        // k = 1024: j=512 intra-thread, j=256..32 smem, j<=16 registers
        e0 = a[tid]; e1 = a[tid + 512];
        if (e0 > e1) { unsigned long long t = e0; e0 = e1; e1 = t; }  // up=true
        a[tid] = e0; a[tid + 512] = e1;
        __syncthreads();
        for (int j = 256; j >= 32; j >>= 1) {
            #pragma unroll
            for (int r = 0; r < 2; ++r) {
                int s = tid + r * 512;
                int l = s ^ j;
                if (l > s) {
                    unsigned long long va = a[s], vb = a[l];
                    if (va > vb) { a[s] = vb; a[l] = va; }   // up=true for k=1024
                }
            }
            __syncthreads();
        }
        e0 = a[tid]; e1 = a[tid + 512];
        #pragma unroll
        for (int j = 16; j > 0; j >>= 1) {
            e0 = bitonic_shfl_step(e0, tid, 1024, j);
            e1 = bitonic_shfl_step(e1, tid + 512, 1024, j);
        }
        g_skey0[(size_t)b * F0 + tid] = e0;
        g_skey0[(size_t)b * F0 + tid + 512] = e1;
        return;
    }

    // ---- mask blocks: 4 edges per thread, transposed mask write ----
    int warp = tid >> 5, lane = tid & 31;
    int o, wslice, log2in, outn;
    const float* etc; const float* otc;
    uint32_t ek0, ek1, opk0, opk1;
    uint32_t* maskb; int* oparr;
    if (bid < 384) {              // layer 0: out=512, in=1024, 8 warps per o
        int q = bid - 128;
        o = q * 2 + (warp >> 3); wslice = warp & 7;
        log2in = 10; outn = F1; etc = etc0; otc = otc0;
        ek0 = e0k0; ek1 = e0k1; opk0 = op0k0; opk1 = op0k1;
        maskb = g_mask0; oparr = g_op0;
    } else {                      // layer 1: out=1024, in=512, 4 warps per o
        int q = bid - 384;
        o = q * 4 + (warp >> 2); wslice = warp & 3;
        log2in = 9; outn = F0; etc = etc1; otc = otc1;
        ek0 = e1k0; ek1 = e1k1; opk0 = op1k0; opk1 = op1k1;
        maskb = g_mask1; oparr = g_op1;
    }

    uint32_t jv = tfbits(opk0, opk1, (uint32_t)(2 * o) + (uint32_t)(lane & 1));
    uint32_t ob0 = __shfl_sync(0xffffffffu, jv, 0);
    uint32_t ob1 = __shfl_sync(0xffffffffu, jv, 1);
    int op = decide(otc[2 * o], otc[2 * o + 1], ob0, ob1) ? 1 : 0;
    if (wslice == 0 && lane == 0) oparr[o] = op;

    uint32_t mbase = ((uint32_t)(o * 2 + op)) << log2in;
    const float2* etc2 = (const float2*)etc;

    #pragma unroll
    for (int c = 0; c < 4; ++c) {
        int i = wslice * 128 + c * 32 + lane;
        uint32_t m = mbase + (uint32_t)i;
        uint32_t b0 = tfbits(ek0, ek1, 2u * m);
        uint32_t b1 = tfbits(ek0, ek1, 2u * m + 1u);
        float2 cc = etc2[m];
        bool sel = decide(cc.x, cc.y, b0, b1);
        unsigned msk = __ballot_sync(0xffffffffu, sel);
        if (lane == 0) maskb[(i >> 5) * outn + o] = msk;   // transposed
    }
}

// ---------------------------------------------------------------------------
// cp.async helpers
// ---------------------------------------------------------------------------
__device__ __forceinline__ uint32_t smem_u32(const void* p) {
    return (uint32_t)__cvta_generic_to_shared(p);
}
__device__ __forceinline__ void cpa16(uint32_t s, const void* g) {
    asm volatile("cp.async.cg.shared.global [%0], [%1], 16;" :: "r"(s), "l"(g));
}
#define CPA_COMMIT() asm volatile("cp.async.commit_group;")
#define CPA_WAIT(n)  asm volatile("cp.async.wait_group %0;" :: "n"(n))

// ---------------------------------------------------------------------------
// Batched per-thread probe; mask in TRANSPOSED smem [w][o] (conflict-free:
// idx warp-uniform, o = lane-varying -> bank = o % 32).
// ---------------------------------------------------------------------------
__device__ __forceinline__ float probe8t(const unsigned long long* __restrict__ a,
                                         int n, const uint32_t* __restrict__ mt,
                                         int outn, int o, int op) {
    float res;
    if (op == 0) {
        res = 1.0f;
        for (int base = 0; base < n; base += 8) {
            unsigned long long kv[8];
            uint32_t w[8];
            #pragma unroll
            for (int t = 0; t < 8; ++t) kv[t] = a[base + t];
            #pragma unroll
            for (int t = 0; t < 8; ++t) {
                unsigned idx = (unsigned)kv[t];
                w[t] = mt[(idx >> 5) * outn + o] >> (idx & 31);
            }
            bool found = false;
            #pragma unroll
            for (int t = 0; t < 8; ++t)
                if (!found && (w[t] & 1u)) {
                    res = __uint_as_float((unsigned)(kv[t] >> 32));
                    found = true;
                }
            if (found) break;
        }
    } else {
        res = 0.0f;
        for (int base = n - 8; base >= 0; base -= 8) {
            unsigned long long kv[8];
            uint32_t w[8];
            #pragma unroll
            for (int t = 0; t < 8; ++t) kv[t] = a[base + 7 - t];
            #pragma unroll
            for (int t = 0; t < 8; ++t) {
                unsigned idx = (unsigned)kv[t];
                w[t] = mt[(idx >> 5) * outn + o] >> (idx & 31);
            }
            bool found = false;
            #pragma unroll
            for (int t = 0; t < 8; ++t)
                if (!found && (w[t] & 1u)) {
                    res = __uint_as_float((unsigned)(kv[t] >> 32));
                    found = true;
                }
            if (found) break;
        }
    }
    return res;
}

// ---------------------------------------------------------------------------
// FUSED kernel: 128 blocks (1/row), 512 threads, 140KB dynamic smem.
// smem: a[1024] (8KB) | hk[512] (4KB) | m0 transposed (64KB) | m1 transposed (64KB)
// ---------------------------------------------------------------------------
extern __shared__ __align__(16) char s_raw[];

__global__ __launch_bounds__(512) void fused_kernel(float* __restrict__ out) {
    unsigned long long* a  = (unsigned long long*)(s_raw);
    unsigned long long* hk = (unsigned long long*)(s_raw + 8192);
    uint32_t* m0s = (uint32_t*)(s_raw + 12288);
    uint32_t* m1s = (uint32_t*)(s_raw + 12288 + 65536);

    int row = blockIdx.x;
    int tid = threadIdx.x;

    {
        const char* gsk = (const char*)(g_skey0 + (size_t)row * F0);
        cpa16(smem_u32((char*)a + tid * 16), gsk + tid * 16);
        CPA_COMMIT();
        #pragma unroll
        for (int r = 0; r < 8; ++r)
            cpa16(smem_u32((char*)m0s + (tid + r * 512) * 16),
                  (const char*)g_mask0 + (tid + r * 512) * 16);
        CPA_COMMIT();
        #pragma unroll
        for (int r = 0; r < 8; ++r)
            cpa16(smem_u32((char*)m1s + (tid + r * 512) * 16),
                  (const char*)g_mask1 + (tid + r * 512) * 16);
        CPA_COMMIT();
    }
    CPA_WAIT(1);          // keys + mask0 resident; mask1 still streaming
    __syncthreads();

    // probe layer 0 (1 neuron per thread)
    unsigned long long v;
    {
        int o = tid;
        int op = g_op0[o];
        float res = probe8t(a, F0, m0s, F1, o, op);
        v = ((unsigned long long)__float_as_uint(res) << 32) | (unsigned)o;
    }

    // bitonic sort 512: k<=32 in registers
    #pragma unroll
    for (int k = 2; k <= 32; k <<= 1)
        #pragma unroll
        for (int j = k >> 1; j > 0; j >>= 1)
            v = bitonic_shfl_step(v, tid, k, j);

    hk[tid] = v;
    __syncthreads();

    #pragma unroll
    for (int k = 64; k <= 512; k <<= 1) {
        for (int j = k >> 1; j >= 32; j >>= 1) {
            int s = tid, l = tid ^ j;
            if (l > s) {
                bool up = ((s & k) == 0);
                unsigned long long va = hk[s], vb = hk[l];
                if ((va > vb) == up) { hk[s] = vb; hk[l] = va; }
            }
            __syncthreads();
        }
        v = hk[tid];
        #pragma unroll
        for (int j = 16; j > 0; j >>= 1)
            v = bitonic_shfl_step(v, tid, k, j);
        hk[tid] = v;
        __syncthreads();
    }

    CPA_WAIT(0);          // mask1 resident
    __syncthreads();

    // probe layer 1 (2 neurons per thread) -> final output
    #pragma unroll
    for (int rep = 0; rep < 2; ++rep) {
        int o = tid + rep * 512;
        int op = g_op1[o];
        float res = probe8t(hk, F1, m1s, F0, o, op);
        out[(size_t)row * F0 + o] = res;
    }
}

// ---------------------------------------------------------------------------
extern "C" void kernel_launch(void* const* d_in, const int* in_sizes, int n_in,
                              void* d_out, int out_size) {
    const float* x    = (const float*)d_in[0];
    const float* etc0 = (const float*)d_in[1];
    const float* otc0 = (const float*)d_in[2];
    const float* etc1 = (const float*)d_in[3];
    const float* otc1 = (const float*)d_in[4];
    float* out = (float*)d_out;

    uint32_t l0k0, l0k1, l1k0, l1k1;
    tf2x32(0u, 42u, 0u, 0u, l0k0, l0k1);
    tf2x32(0u, 42u, 0u, 1u, l1k0, l1k1);
    uint32_t op0k0, op0k1, e0k0, e0k1;
    tf2x32(l0k0, l0k1, 0u, 0u, op0k0, op0k1);
    tf2x32(l0k0, l0k1, 0u, 1u, e0k0,  e0k1);
    uint32_t op1k0, op1k1, e1k0, e1k1;
    tf2x32(l1k0, l1k1, 0u, 0u, op1k0, op1k1);
    tf2x32(l1k0, l1k1, 0u, 1u, e1k0,  e1k1);

    static bool attr_set = false;
    if (!attr_set) {
        cudaFuncSetAttribute(fused_kernel,
                             cudaFuncAttributeMaxDynamicSharedMemorySize,
                             12288 + 65536 + 65536);
        attr_set = true;
    }

    mega_kernel<<<640, 512>>>(x, etc0, otc0, etc1, otc1,
                              op0k0, op0k1, e0k0, e0k1,
                              op1k0, op1k1, e1k0, e1k1);
    fused_kernel<<<B_SZ, 512, 12288 + 65536 + 65536>>>(out);
}